// round 13
// baseline (speedup 1.0000x reference)
#include <cuda_runtime.h>
#include <cuda_fp16.h>
#include <cstdint>

// ---------------------------------------------------------------------------
// Problem constants
// ---------------------------------------------------------------------------
#define B_  4
#define T_  2048
#define C_  768
#define H_  12
#define D_  64
#define M_  (B_ * T_)          // 8192
#define QSCALE (0.125f * 1.4426950408889634f)   // 1/sqrt(64) * log2(e)

// ---------------------------------------------------------------------------
// Scratch device globals.  fp16 scheme:
//   QKV proj:  acc = f16(x) * f16(W)          (1-term, error budgeted)
//   out proj:  acc = f16(O) * (Wo_hi + Wo_lo) (2-term)
//   flash:     S = qh*(kh+kl),  O += f16(P)*(vh+vl)
// ---------------------------------------------------------------------------
__device__ __half g_Xh[(size_t)M_ * C_];                 // x, hi only
__device__ __half g_Whi[4 * (size_t)C_ * C_];            // Wq,Wk,Wv,Wo hi
__device__ __half g_Wlo[(size_t)C_ * C_];                // Wo lo only

__device__ __half g_Qh[(size_t)B_ * H_ * T_ * D_];       // Q hi only (pre-scaled)
__device__ __half g_Kh[(size_t)B_ * H_ * T_ * D_];       // K hi
__device__ __half g_Kl[(size_t)B_ * H_ * T_ * D_];       // K lo
__device__ __half g_Vh[(size_t)B_ * H_ * T_ * D_];       // V hi
__device__ __half g_Vl[(size_t)B_ * H_ * T_ * D_];       // V lo

__device__ __half g_Oh[(size_t)M_ * C_];                 // attn out, hi only

// ---------------------------------------------------------------------------
// PTX helpers
// ---------------------------------------------------------------------------
__device__ __forceinline__ uint32_t smem_u32(const void* p) {
    uint32_t a;
    asm("{ .reg .u64 t; cvta.to.shared.u64 t, %1; cvt.u32.u64 %0, t; }"
        : "=r"(a) : "l"(p));
    return a;
}

#define CP_ASYNC16(dst, src) \
    asm volatile("cp.async.cg.shared.global [%0], [%1], 16;" \
                 :: "r"(dst), "l"(src) : "memory")
#define CP_COMMIT() asm volatile("cp.async.commit_group;" ::: "memory")
#define CP_WAIT(n)  asm volatile("cp.async.wait_group %0;" :: "n"(n) : "memory")

__device__ __forceinline__ void ldsm_x4(uint32_t* r, uint32_t addr) {
    asm volatile("ldmatrix.sync.aligned.m8n8.x4.shared.b16 {%0,%1,%2,%3}, [%4];"
                 : "=r"(r[0]), "=r"(r[1]), "=r"(r[2]), "=r"(r[3]) : "r"(addr));
}

__device__ __forceinline__ void ldsm_x4_trans(uint32_t* r, uint32_t addr) {
    asm volatile("ldmatrix.sync.aligned.m8n8.x4.trans.shared.b16 {%0,%1,%2,%3}, [%4];"
                 : "=r"(r[0]), "=r"(r[1]), "=r"(r[2]), "=r"(r[3]) : "r"(addr));
}

__device__ __forceinline__ void mma_f16(float* c, const uint32_t* a, const uint32_t* b) {
    asm volatile(
        "mma.sync.aligned.m16n8k16.row.col.f32.f16.f16.f32 "
        "{%0,%1,%2,%3}, {%4,%5,%6,%7}, {%8,%9}, {%0,%1,%2,%3};"
        : "+f"(c[0]), "+f"(c[1]), "+f"(c[2]), "+f"(c[3])
        : "r"(a[0]), "r"(a[1]), "r"(a[2]), "r"(a[3]), "r"(b[0]), "r"(b[1]));
}

__device__ __forceinline__ float ex2(float x) {          // raw MUFU.EX2
    float y;
    asm("ex2.approx.f32 %0, %1;" : "=f"(y) : "f"(x));
    return y;
}

__device__ __forceinline__ uint32_t pack_f16x2(float lo, float hi) {
    uint32_t r;
    asm("cvt.rn.f16x2.f32 %0, %1, %2;" : "=r"(r) : "f"(hi), "f"(lo));
    return r;
}
__device__ __forceinline__ uint32_t residual_pack_f16(uint32_t hipack, float lo, float hi) {
    __half2 h2 = *reinterpret_cast<__half2*>(&hipack);
    float rlo = lo - __half2float(__low2half(h2));
    float rhi = hi - __half2float(__high2half(h2));
    return pack_f16x2(rlo, rhi);
}

// ---------------------------------------------------------------------------
// Converters
// ---------------------------------------------------------------------------
__global__ void cvt_x_kernel(const float* __restrict__ src) {
    size_t i = (size_t)blockIdx.x * blockDim.x + threadIdx.x;
    g_Xh[i] = __float2half(src[i]);
}

__global__ void cvt_w_kernel(const float* __restrict__ Wq, const float* __restrict__ Wk,
                             const float* __restrict__ Wv, const float* __restrict__ Wo) {
    const float* src = (blockIdx.y == 0) ? Wq : (blockIdx.y == 1) ? Wk
                      : (blockIdx.y == 2) ? Wv : Wo;
    size_t off = (size_t)blockIdx.y * C_ * C_;
    size_t i = (size_t)blockIdx.x * blockDim.x + threadIdx.x;
    float v = src[i];
    __half h = __float2half(v);
    g_Whi[off + i] = h;
    if (blockIdx.y == 3)                      // lo kept only for Wo
        g_Wlo[i] = __float2half(v - __half2float(h));
}

// ---------------------------------------------------------------------------
// GEMM via mma.sync.  BK=64 (12 chunks), CTA 128x128, 256 threads,
// double-buffered, register-staged prefetch.
// mode 0 (QKV): 1-term f16 (no B-lo).  mode 1 (out proj): 2-term.
// ---------------------------------------------------------------------------
#define BK      64
#define NCHUNK  (C_ / BK)      // 12
#define A_STRIDE 144           // 64 f16 + 8 pad -> 9 x 16B, conflict-free
#define B_STRIDE 272           // 128 f16 + 8 pad -> 17 x 16B
#define SM_BHI   18432         // after A hi: 128*144
#define SM_BLO   35840         // + 64*272
#define SM_STAGE 53248
#define SM_TOTAL (2 * SM_STAGE)   // 106496

__global__ __launch_bounds__(256, 1)
void tc_gemm_kernel(int mode, float* __restrict__ out_final,
                    const float* __restrict__ b0, const float* __restrict__ b1,
                    const float* __restrict__ b2)
{
    extern __shared__ char smem[];
    const uint32_t sb = smem_u32(smem);
    const int tid  = threadIdx.x;
    const int lane = tid & 31;
    const int w    = tid >> 5;
    const int wm   = (w & 3) * 32;
    const int wn   = (w >> 2) * 64;

    const int z    = blockIdx.z;
    const int widx = (mode == 0) ? z : 3;
    const bool use_blo = (mode != 0);
    const __half* Ah  = (mode == 0) ? g_Xh : g_Oh;
    const __half* Whi = g_Whi + (size_t)widx * C_ * C_;
    const __half* Wlo = g_Wlo;
    const float* bias = (mode == 0) ? ((z == 0) ? b0 : (z == 1) ? b1 : b2) : b0;

    const int bm = blockIdx.y * 128;
    const int bn = blockIdx.x * 128;

    float acc[2][8][4];
    #pragma unroll
    for (int i = 0; i < 2; i++)
        #pragma unroll
        for (int j = 0; j < 8; j++)
            #pragma unroll
            for (int r = 0; r < 4; r++) acc[i][j][r] = 0.f;

    const int au = tid & 7;
    const int ar = tid >> 3;
    const int bu = tid & 15;
    const int br = tid >> 4;

    const uint32_t aAddr0 = (uint32_t)((wm + (lane & 15)) * A_STRIDE + (lane >> 4) * 16);
    const uint32_t bAddr0 = (uint32_t)(((lane & 7) + ((lane >> 3) & 1) * 8) * B_STRIDE
                                       + (wn + (lane >> 4) * 8) * 2);

    // ---- prologue: chunk 0 into stage 0 ----
    {
        #pragma unroll
        for (int h = 0; h < 4; h++) {
            const int row = ar + h * 32;
            *(uint4*)(smem + row * A_STRIDE + au * 16) =
                *(const uint4*)(Ah + (size_t)(bm + row) * C_ + au * 8);
        }
        #pragma unroll
        for (int h = 0; h < 4; h++) {
            const int row = br + h * 16;
            const size_t gb = (size_t)row * C_ + bn + bu * 8;
            *(uint4*)(smem + SM_BHI + row * B_STRIDE + bu * 16) = *(const uint4*)(Whi + gb);
            if (use_blo)
                *(uint4*)(smem + SM_BLO + row * B_STRIDE + bu * 16) = *(const uint4*)(Wlo + gb);
        }
    }
    __syncthreads();

    for (int c = 0; c < NCHUNK; ++c) {
        // ---- register-staged prefetch of next chunk ----
        uint4 nA[4], nBhi[4], nBlo[4];
        if (c + 1 < NCHUNK) {
            const int k0 = (c + 1) * BK;
            #pragma unroll
            for (int h = 0; h < 4; h++) {
                const int row = ar + h * 32;
                nA[h] = *(const uint4*)(Ah + (size_t)(bm + row) * C_ + k0 + au * 8);
            }
            #pragma unroll
            for (int h = 0; h < 4; h++) {
                const int row = br + h * 16;
                const size_t gb = (size_t)(k0 + row) * C_ + bn + bu * 8;
                nBhi[h] = *(const uint4*)(Whi + gb);
                if (use_blo) nBlo[h] = *(const uint4*)(Wlo + gb);
            }
        }

        // ---- compute current chunk: 4 k-steps of 16 ----
        const uint32_t stg = sb + (c & 1) * SM_STAGE;
        if (!use_blo) {
            #pragma unroll
            for (int kk = 0; kk < 4; kk++) {
                uint32_t ah[2][4], bh[8][2];
                #pragma unroll
                for (int i = 0; i < 2; i++)
                    ldsm_x4(ah[i], stg + aAddr0 + i * 16 * A_STRIDE + kk * 32);
                #pragma unroll
                for (int jj = 0; jj < 4; jj++) {
                    uint32_t t[4];
                    ldsm_x4_trans(t, stg + SM_BHI + bAddr0 + kk * 16 * B_STRIDE + jj * 32);
                    bh[jj * 2][0] = t[0]; bh[jj * 2][1] = t[1];
                    bh[jj * 2 + 1][0] = t[2]; bh[jj * 2 + 1][1] = t[3];
                }
                #pragma unroll
                for (int i = 0; i < 2; i++)
                    #pragma unroll
                    for (int j = 0; j < 8; j++)
                        mma_f16(acc[i][j], ah[i], bh[j]);
            }
        } else {
            #pragma unroll
            for (int kk = 0; kk < 4; kk++) {
                uint32_t ah[2][4], bh[8][2], bl[8][2];
                #pragma unroll
                for (int i = 0; i < 2; i++)
                    ldsm_x4(ah[i], stg + aAddr0 + i * 16 * A_STRIDE + kk * 32);
                #pragma unroll
                for (int jj = 0; jj < 4; jj++) {
                    uint32_t t[4];
                    const uint32_t boff = bAddr0 + kk * 16 * B_STRIDE + jj * 32;
                    ldsm_x4_trans(t, stg + SM_BHI + boff);
                    bh[jj * 2][0] = t[0]; bh[jj * 2][1] = t[1];
                    bh[jj * 2 + 1][0] = t[2]; bh[jj * 2 + 1][1] = t[3];
                    ldsm_x4_trans(t, stg + SM_BLO + boff);
                    bl[jj * 2][0] = t[0]; bl[jj * 2][1] = t[1];
                    bl[jj * 2 + 1][0] = t[2]; bl[jj * 2 + 1][1] = t[3];
                }
                #pragma unroll
                for (int i = 0; i < 2; i++)
                    #pragma unroll
                    for (int j = 0; j < 8; j++) {
                        mma_f16(acc[i][j], ah[i], bh[j]);
                        mma_f16(acc[i][j], ah[i], bl[j]);
                    }
            }
        }

        // ---- store prefetched chunk into the other stage ----
        if (c + 1 < NCHUNK) {
            char* dst = smem + ((c + 1) & 1) * SM_STAGE;
            #pragma unroll
            for (int h = 0; h < 4; h++) {
                const int row = ar + h * 32;
                *(uint4*)(dst + row * A_STRIDE + au * 16) = nA[h];
            }
            #pragma unroll
            for (int h = 0; h < 4; h++) {
                const int row = br + h * 16;
                *(uint4*)(dst + SM_BHI + row * B_STRIDE + bu * 16) = nBhi[h];
                if (use_blo)
                    *(uint4*)(dst + SM_BLO + row * B_STRIDE + bu * 16) = nBlo[h];
            }
        }
        __syncthreads();
    }

    // ---- epilogue ----
    #pragma unroll
    for (int i = 0; i < 2; i++) {
        const int r0 = bm + wm + i * 16 + (lane >> 2);
        #pragma unroll
        for (int j = 0; j < 8; j++) {
            const int col = bn + wn + j * 8 + (lane & 3) * 2;
            const float bx = bias[col], by = bias[col + 1];
            if (mode == 0) {
                const int h = col >> 6;
                const int d = col & 63;
                #pragma unroll
                for (int half = 0; half < 2; half++) {
                    const int m  = r0 + half * 8;
                    const int bi = m >> 11;
                    const int tt = m & (T_ - 1);
                    float v0 = acc[i][j][half * 2] + bx;
                    float v1 = acc[i][j][half * 2 + 1] + by;
                    const size_t idx = (((size_t)bi * H_ + h) * T_ + tt) * D_ + d;
                    if (z == 0) {
                        *(uint32_t*)(g_Qh + idx) = pack_f16x2(v0 * QSCALE, v1 * QSCALE);
                    } else {
                        __half* hiA = (z == 1) ? g_Kh : g_Vh;
                        __half* loA = (z == 1) ? g_Kl : g_Vl;
                        uint32_t uhi = pack_f16x2(v0, v1);
                        *(uint32_t*)(hiA + idx) = uhi;
                        *(uint32_t*)(loA + idx) = residual_pack_f16(uhi, v0, v1);
                    }
                }
            } else {
                #pragma unroll
                for (int half = 0; half < 2; half++) {
                    const int m = r0 + half * 8;
                    float2 v = make_float2(acc[i][j][half * 2] + bx,
                                           acc[i][j][half * 2 + 1] + by);
                    *(float2*)(out_final + (size_t)m * C_ + col) = v;
                }
            }
        }
    }
}

// ---------------------------------------------------------------------------
// Flash attention on mma.sync, fp16 2-term.  Softmax overhead trimmed:
// deferred l-reduction (per-thread partials, one shuffle pass at the end)
// and conditional O-rescale (skipped when the running max didn't grow).
// 128-thread CTAs (4 warps, 64 q-rows), 2 CTAs/SM, 2-stage cp.async K/V ring.
// ---------------------------------------------------------------------------
#define FSTR     144             // 72 f16 row stride (odd 16B multiple)
#define FS_KV    9216            // Q hi: 64*144 = 9216 @ 0; stages follow
#define FS_KLO_O 9216
#define FS_VHI_O 18432
#define FS_VLO_O 27648
#define FS_STAGE 36864
#define FS_TOTAL (FS_KV + 2 * FS_STAGE)   // 82944

__global__ __launch_bounds__(128, 2)
void flash_mma_kernel()
{
    extern __shared__ char smem[];
    const uint32_t sb = smem_u32(smem);
    const int tid  = threadIdx.x;
    const int lane = tid & 31;
    const int w    = tid >> 5;                               // 0..3
    const int qt   = (int)gridDim.x - 1 - (int)blockIdx.x;   // big tiles first
    const int bh   = blockIdx.y;
    const int q0   = qt * 64;
    const int nch  = qt + 1;                                 // 64-key chunks

    const size_t headoff = (size_t)bh * T_ * D_;
    const __half* Kh = g_Kh + headoff;
    const __half* Kl = g_Kl + headoff;
    const __half* Vh = g_Vh + headoff;
    const __half* Vl = g_Vl + headoff;

    auto issue_kv = [&](int kt, uint32_t stg) {
        #pragma unroll
        for (int i = 0; i < 4; i++) {
            const int e = tid + i * 128;     // 0..511
            const int row = e >> 3, u = e & 7;
            const size_t g = (size_t)(kt + row) * D_ + u * 8;
            const uint32_t o = (uint32_t)(row * FSTR + u * 16);
            CP_ASYNC16(stg + o,            Kh + g);
            CP_ASYNC16(stg + FS_KLO_O + o, Kl + g);
            CP_ASYNC16(stg + FS_VHI_O + o, Vh + g);
            CP_ASYNC16(stg + FS_VLO_O + o, Vl + g);
        }
    };

    issue_kv(0, sb + FS_KV);
    CP_COMMIT();

    // ---- stage Q tile (64 x 64, hi only) ----
    {
        const __half* Qh = g_Qh + headoff + (size_t)q0 * D_;
        #pragma unroll
        for (int i = 0; i < 4; i++) {
            const int e = tid + i * 128;
            const int row = e >> 3, u = e & 7;
            *(uint4*)(smem + row * FSTR + u * 16) = *(const uint4*)(Qh + row * 64 + u * 8);
        }
    }
    __syncthreads();

    // ---- Q fragments (registers for the whole loop) ----
    uint32_t qh[4][4];
    {
        const uint32_t qa = sb + (uint32_t)((16 * w + (lane & 15)) * FSTR + (lane >> 4) * 16);
        #pragma unroll
        for (int s = 0; s < 4; s++) ldsm_x4(qh[s], qa + s * 32);
    }

    float O[8][4];
    #pragma unroll
    for (int j = 0; j < 8; j++)
        #pragma unroll
        for (int r = 0; r < 4; r++) O[j][r] = 0.f;
    float m0 = -1e30f, m1 = -1e30f;
    float l0p = 0.f, l1p = 0.f;          // per-thread partial denominators

    const int wrow = q0 + 16 * w;
    const int r0g  = wrow + (lane >> 2);
    const int r1g  = r0g + 8;

    for (int c = 0; c < nch; ++c) {
        if (c + 1 < nch) {
            issue_kv((c + 1) * 64, sb + FS_KV + ((c + 1) & 1) * FS_STAGE);
            CP_COMMIT();
            CP_WAIT(1);
        } else {
            CP_WAIT(0);
        }
        __syncthreads();

        const int kt = c * 64;
        if (kt <= wrow + 15) {
            const uint32_t kbase = sb + FS_KV + (c & 1) * FS_STAGE;
            const int kmax = wrow + 15 - kt;

            // ---- S = qh * (kh + kl), s-outer ----
            float S[8][4];
            #pragma unroll
            for (int j = 0; j < 8; j++)
                #pragma unroll
                for (int r = 0; r < 4; r++) S[j][r] = 0.f;

            #pragma unroll
            for (int s = 0; s < 4; s++) {
                uint32_t kh[4][4], kl[4][4];
                #pragma unroll
                for (int kp = 0; kp < 4; kp++) {
                    if (kp * 16 > kmax) continue;
                    const uint32_t ka = kbase
                        + (uint32_t)((kp * 16 + (lane & 15)) * FSTR + (lane >> 4) * 16)
                        + s * 32;
                    ldsm_x4(kh[kp], ka);
                    ldsm_x4(kl[kp], ka + FS_KLO_O);
                }
                #pragma unroll
                for (int kp = 0; kp < 4; kp++) {
                    if (kp * 16 > kmax) continue;
                    uint32_t be[2] = {kh[kp][0], kh[kp][2]}, bo[2] = {kh[kp][1], kh[kp][3]};
                    uint32_t le[2] = {kl[kp][0], kl[kp][2]}, lo_[2] = {kl[kp][1], kl[kp][3]};
                    mma_f16(S[2 * kp],     qh[s], be);
                    mma_f16(S[2 * kp + 1], qh[s], bo);
                    mma_f16(S[2 * kp],     qh[s], le);
                    mma_f16(S[2 * kp + 1], qh[s], lo_);
                }
            }

            // ---- causal mask ----
            if (kt + 63 > wrow) {
                #pragma unroll
                for (int j = 0; j < 8; j++) {
                    const int c0 = kt + j * 8 + (lane & 3) * 2;
                    if (c0 > r0g)     S[j][0] = -1e30f;
                    if (c0 + 1 > r0g) S[j][1] = -1e30f;
                    if (c0 > r1g)     S[j][2] = -1e30f;
                    if (c0 + 1 > r1g) S[j][3] = -1e30f;
                }
            }

            // ---- online softmax (base-2; raw EX2; deferred l-reduction) ----
            float vmax0 = -1e30f, vmax1 = -1e30f;
            #pragma unroll
            for (int j = 0; j < 8; j++) {
                vmax0 = fmaxf(vmax0, fmaxf(S[j][0], S[j][1]));
                vmax1 = fmaxf(vmax1, fmaxf(S[j][2], S[j][3]));
            }
            vmax0 = fmaxf(vmax0, __shfl_xor_sync(0xffffffffu, vmax0, 1));
            vmax0 = fmaxf(vmax0, __shfl_xor_sync(0xffffffffu, vmax0, 2));
            vmax1 = fmaxf(vmax1, __shfl_xor_sync(0xffffffffu, vmax1, 1));
            vmax1 = fmaxf(vmax1, __shfl_xor_sync(0xffffffffu, vmax1, 2));

            const float mn0 = fmaxf(m0, vmax0);
            const float mn1 = fmaxf(m1, vmax1);
            const bool grow = (vmax0 > m0) || (vmax1 > m1);   // quad-uniform
            const float c0f = ex2(m0 - mn0);
            const float c1f = ex2(m1 - mn1);
            m0 = mn0; m1 = mn1;

            float sum0 = 0.f, sum1 = 0.f;
            float P[8][4];
            #pragma unroll
            for (int j = 0; j < 8; j++) {
                P[j][0] = ex2(S[j][0] - mn0);
                P[j][1] = ex2(S[j][1] - mn0);
                P[j][2] = ex2(S[j][2] - mn1);
                P[j][3] = ex2(S[j][3] - mn1);
                sum0 += P[j][0] + P[j][1];
                sum1 += P[j][2] + P[j][3];
            }
            l0p = l0p * c0f + sum0;
            l1p = l1p * c1f + sum1;

            if (grow) {
                #pragma unroll
                for (int j = 0; j < 8; j++) {
                    O[j][0] *= c0f; O[j][1] *= c0f;
                    O[j][2] *= c1f; O[j][3] *= c1f;
                }
            }

            // ---- P fragments (hi only) ----
            uint32_t pa[4][4];
            #pragma unroll
            for (int kp = 0; kp < 4; kp++) {
                if (kp * 16 > kmax) continue;
                pa[kp][0] = pack_f16x2(P[2 * kp][0],     P[2 * kp][1]);
                pa[kp][1] = pack_f16x2(P[2 * kp][2],     P[2 * kp][3]);
                pa[kp][2] = pack_f16x2(P[2 * kp + 1][0], P[2 * kp + 1][1]);
                pa[kp][3] = pack_f16x2(P[2 * kp + 1][2], P[2 * kp + 1][3]);
            }

            // ---- O += P * (vh + vl) ----
            #pragma unroll
            for (int kp = 0; kp < 4; kp++) {
                if (kp * 16 > kmax) continue;
                const uint32_t va0 = kbase + FS_VHI_O
                    + (uint32_t)((kp * 16 + (lane & 7) + ((lane >> 3) & 1) * 8) * FSTR
                                 + (lane >> 4) * 16);
                #pragma unroll
                for (int db = 0; db < 4; db++) {
                    uint32_t vh[4], vl[4];
                    ldsm_x4_trans(vh, va0 + db * 32);
                    ldsm_x4_trans(vl, va0 + db * 32 + (FS_VLO_O - FS_VHI_O));
                    uint32_t bh0[2] = {vh[0], vh[1]}, bh1[2] = {vh[2], vh[3]};
                    uint32_t bl0[2] = {vl[0], vl[1]}, bl1[2] = {vl[2], vl[3]};
                    mma_f16(O[2 * db],     pa[kp], bh0);
                    mma_f16(O[2 * db + 1], pa[kp], bh1);
                    mma_f16(O[2 * db],     pa[kp], bl0);
                    mma_f16(O[2 * db + 1], pa[kp], bl1);
                }
            }
        }
        __syncthreads();
    }

    // ---- final l reduction across the quad, then epilogue ----
    l0p += __shfl_xor_sync(0xffffffffu, l0p, 1);
    l0p += __shfl_xor_sync(0xffffffffu, l0p, 2);
    l1p += __shfl_xor_sync(0xffffffffu, l1p, 1);
    l1p += __shfl_xor_sync(0xffffffffu, l1p, 2);
    const float inv0 = 1.f / l0p;
    const float inv1 = 1.f / l1p;
    const int bi = bh / H_;
    const int h  = bh % H_;
    #pragma unroll
    for (int jd = 0; jd < 8; jd++) {
        const int d0 = jd * 8 + (lane & 3) * 2;
        {
            const size_t idx = ((size_t)bi * T_ + r0g) * C_ + h * 64 + d0;
            *(uint32_t*)(g_Oh + idx) = pack_f16x2(O[jd][0] * inv0, O[jd][1] * inv0);
        }
        {
            const size_t idx = ((size_t)bi * T_ + r1g) * C_ + h * 64 + d0;
            *(uint32_t*)(g_Oh + idx) = pack_f16x2(O[jd][2] * inv1, O[jd][3] * inv1);
        }
    }
}

// ---------------------------------------------------------------------------
// Launch
// ---------------------------------------------------------------------------
extern "C" void kernel_launch(void* const* d_in, const int* in_sizes, int n_in,
                              void* d_out, int out_size)
{
    const float* x  = (const float*)d_in[0];
    const float* Wq = (const float*)d_in[1];
    const float* bq = (const float*)d_in[2];
    const float* Wk = (const float*)d_in[3];
    const float* bk = (const float*)d_in[4];
    const float* Wv = (const float*)d_in[5];
    const float* bv = (const float*)d_in[6];
    const float* Wo = (const float*)d_in[7];
    const float* bo = (const float*)d_in[8];

    static bool attr_set = false;
    if (!attr_set) {
        cudaFuncSetAttribute(tc_gemm_kernel,
                             cudaFuncAttributeMaxDynamicSharedMemorySize, SM_TOTAL);
        cudaFuncSetAttribute(flash_mma_kernel,
                             cudaFuncAttributeMaxDynamicSharedMemorySize, FS_TOTAL);
        attr_set = true;
    }

    cvt_x_kernel<<<(M_ * C_) / 1024, 1024>>>(x);
    cvt_w_kernel<<<dim3((C_ * C_) / 1024, 4), 1024>>>(Wq, Wk, Wv, Wo);

    tc_gemm_kernel<<<dim3(C_ / 128, M_ / 128, 3), 256, SM_TOTAL>>>(
        0, nullptr, bq, bk, bv);

    flash_mma_kernel<<<dim3(T_ / 64, B_ * H_), 128, FS_TOTAL>>>();

    tc_gemm_kernel<<<dim3(C_ / 128, M_ / 128, 1), 256, SM_TOTAL>>>(
        1, (float*)d_out, bo, nullptr, nullptr);
}

// round 14
// speedup vs baseline: 1.5184x; 1.5184x over previous
#include <cuda_runtime.h>
#include <cuda_fp16.h>
#include <cstdint>

// ---------------------------------------------------------------------------
// Problem constants
// ---------------------------------------------------------------------------
#define B_  4
#define T_  2048
#define C_  768
#define H_  12
#define D_  64
#define M_  (B_ * T_)          // 8192
#define QSCALE (0.125f * 1.4426950408889634f)   // 1/sqrt(64) * log2(e)

// ---------------------------------------------------------------------------
// Scratch device globals.  fp16 scheme:
//   QKV proj:  acc = f16(x) * f16(W)          (1-term, error budgeted)
//   out proj:  acc = f16(O) * (Wo_hi + Wo_lo) (2-term)
//   flash:     S = qh*(kh+kl),  O += f16(P)*(vh+vl)
// ---------------------------------------------------------------------------
__device__ __half g_Xh[(size_t)M_ * C_];                 // x, hi only
__device__ __half g_Whi[4 * (size_t)C_ * C_];            // Wq,Wk,Wv,Wo hi
__device__ __half g_Wlo[(size_t)C_ * C_];                // Wo lo only

__device__ __half g_Qh[(size_t)B_ * H_ * T_ * D_];       // Q hi only (pre-scaled)
__device__ __half g_Kh[(size_t)B_ * H_ * T_ * D_];       // K hi
__device__ __half g_Kl[(size_t)B_ * H_ * T_ * D_];       // K lo
__device__ __half g_Vh[(size_t)B_ * H_ * T_ * D_];       // V hi
__device__ __half g_Vl[(size_t)B_ * H_ * T_ * D_];       // V lo

__device__ __half g_Oh[(size_t)M_ * C_];                 // attn out, hi only

// ---------------------------------------------------------------------------
// PTX helpers
// ---------------------------------------------------------------------------
__device__ __forceinline__ uint32_t smem_u32(const void* p) {
    uint32_t a;
    asm("{ .reg .u64 t; cvta.to.shared.u64 t, %1; cvt.u32.u64 %0, t; }"
        : "=r"(a) : "l"(p));
    return a;
}

#define CP_ASYNC16(dst, src) \
    asm volatile("cp.async.cg.shared.global [%0], [%1], 16;" \
                 :: "r"(dst), "l"(src) : "memory")
#define CP_COMMIT() asm volatile("cp.async.commit_group;" ::: "memory")
#define CP_WAIT(n)  asm volatile("cp.async.wait_group %0;" :: "n"(n) : "memory")

__device__ __forceinline__ void ldsm_x4(uint32_t* r, uint32_t addr) {
    asm volatile("ldmatrix.sync.aligned.m8n8.x4.shared.b16 {%0,%1,%2,%3}, [%4];"
                 : "=r"(r[0]), "=r"(r[1]), "=r"(r[2]), "=r"(r[3]) : "r"(addr));
}

__device__ __forceinline__ void ldsm_x4_trans(uint32_t* r, uint32_t addr) {
    asm volatile("ldmatrix.sync.aligned.m8n8.x4.trans.shared.b16 {%0,%1,%2,%3}, [%4];"
                 : "=r"(r[0]), "=r"(r[1]), "=r"(r[2]), "=r"(r[3]) : "r"(addr));
}

__device__ __forceinline__ void mma_f16(float* c, const uint32_t* a, const uint32_t* b) {
    asm volatile(
        "mma.sync.aligned.m16n8k16.row.col.f32.f16.f16.f32 "
        "{%0,%1,%2,%3}, {%4,%5,%6,%7}, {%8,%9}, {%0,%1,%2,%3};"
        : "+f"(c[0]), "+f"(c[1]), "+f"(c[2]), "+f"(c[3])
        : "r"(a[0]), "r"(a[1]), "r"(a[2]), "r"(a[3]), "r"(b[0]), "r"(b[1]));
}

__device__ __forceinline__ float ex2(float x) {          // raw MUFU.EX2
    float y;
    asm("ex2.approx.f32 %0, %1;" : "=f"(y) : "f"(x));
    return y;
}

__device__ __forceinline__ uint32_t pack_f16x2(float lo, float hi) {
    uint32_t r;
    asm("cvt.rn.f16x2.f32 %0, %1, %2;" : "=r"(r) : "f"(hi), "f"(lo));
    return r;
}
__device__ __forceinline__ uint32_t residual_pack_f16(uint32_t hipack, float lo, float hi) {
    __half2 h2 = *reinterpret_cast<__half2*>(&hipack);
    float rlo = lo - __half2float(__low2half(h2));
    float rhi = hi - __half2float(__high2half(h2));
    return pack_f16x2(rlo, rhi);
}

// ---------------------------------------------------------------------------
// Converters
// ---------------------------------------------------------------------------
__global__ void cvt_x_kernel(const float* __restrict__ src) {
    size_t i = (size_t)blockIdx.x * blockDim.x + threadIdx.x;
    g_Xh[i] = __float2half(src[i]);
}

__global__ void cvt_w_kernel(const float* __restrict__ Wq, const float* __restrict__ Wk,
                             const float* __restrict__ Wv, const float* __restrict__ Wo) {
    const float* src = (blockIdx.y == 0) ? Wq : (blockIdx.y == 1) ? Wk
                      : (blockIdx.y == 2) ? Wv : Wo;
    size_t off = (size_t)blockIdx.y * C_ * C_;
    size_t i = (size_t)blockIdx.x * blockDim.x + threadIdx.x;
    float v = src[i];
    __half h = __float2half(v);
    g_Whi[off + i] = h;
    if (blockIdx.y == 3)                      // lo kept only for Wo
        g_Wlo[i] = __float2half(v - __half2float(h));
}

// ---------------------------------------------------------------------------
// GEMM via mma.sync.  BK=64 (12 chunks), CTA 128x128, 256 threads,
// double-buffered, register-staged prefetch.  USE_BLO is a compile-time
// template parameter: QKV proj uses the lean 1-term body, out proj 2-term.
// ---------------------------------------------------------------------------
#define BK      64
#define NCHUNK  (C_ / BK)      // 12
#define A_STRIDE 144           // 64 f16 + 8 pad -> 9 x 16B, conflict-free
#define B_STRIDE 272           // 128 f16 + 8 pad -> 17 x 16B
#define SM_BHI   18432         // after A hi: 128*144
#define SM_BLO   35840         // + 64*272
#define SM_STAGE 53248
#define SM_TOTAL (2 * SM_STAGE)   // 106496

template<bool USE_BLO>
__global__ __launch_bounds__(256, 1)
void tc_gemm_kernel(float* __restrict__ out_final,
                    const float* __restrict__ b0, const float* __restrict__ b1,
                    const float* __restrict__ b2)
{
    extern __shared__ char smem[];
    const uint32_t sb = smem_u32(smem);
    const int tid  = threadIdx.x;
    const int lane = tid & 31;
    const int w    = tid >> 5;
    const int wm   = (w & 3) * 32;
    const int wn   = (w >> 2) * 64;

    const int z    = blockIdx.z;
    const int widx = USE_BLO ? 3 : z;
    const __half* Ah  = USE_BLO ? g_Oh : g_Xh;
    const __half* Whi = g_Whi + (size_t)widx * C_ * C_;
    const __half* Wlo = g_Wlo;
    const float* bias = USE_BLO ? b0 : ((z == 0) ? b0 : (z == 1) ? b1 : b2);

    const int bm = blockIdx.y * 128;
    const int bn = blockIdx.x * 128;

    float acc[2][8][4];
    #pragma unroll
    for (int i = 0; i < 2; i++)
        #pragma unroll
        for (int j = 0; j < 8; j++)
            #pragma unroll
            for (int r = 0; r < 4; r++) acc[i][j][r] = 0.f;

    const int au = tid & 7;
    const int ar = tid >> 3;
    const int bu = tid & 15;
    const int br = tid >> 4;

    const uint32_t aAddr0 = (uint32_t)((wm + (lane & 15)) * A_STRIDE + (lane >> 4) * 16);
    const uint32_t bAddr0 = (uint32_t)(((lane & 7) + ((lane >> 3) & 1) * 8) * B_STRIDE
                                       + (wn + (lane >> 4) * 8) * 2);

    // ---- prologue: chunk 0 into stage 0 ----
    {
        #pragma unroll
        for (int h = 0; h < 4; h++) {
            const int row = ar + h * 32;
            *(uint4*)(smem + row * A_STRIDE + au * 16) =
                *(const uint4*)(Ah + (size_t)(bm + row) * C_ + au * 8);
        }
        #pragma unroll
        for (int h = 0; h < 4; h++) {
            const int row = br + h * 16;
            const size_t gb = (size_t)row * C_ + bn + bu * 8;
            *(uint4*)(smem + SM_BHI + row * B_STRIDE + bu * 16) = *(const uint4*)(Whi + gb);
            if (USE_BLO)
                *(uint4*)(smem + SM_BLO + row * B_STRIDE + bu * 16) = *(const uint4*)(Wlo + gb);
        }
    }
    __syncthreads();

    for (int c = 0; c < NCHUNK; ++c) {
        // ---- register-staged prefetch of next chunk ----
        uint4 nA[4], nBhi[4], nBlo[4];
        if (c + 1 < NCHUNK) {
            const int k0 = (c + 1) * BK;
            #pragma unroll
            for (int h = 0; h < 4; h++) {
                const int row = ar + h * 32;
                nA[h] = *(const uint4*)(Ah + (size_t)(bm + row) * C_ + k0 + au * 8);
            }
            #pragma unroll
            for (int h = 0; h < 4; h++) {
                const int row = br + h * 16;
                const size_t gb = (size_t)(k0 + row) * C_ + bn + bu * 8;
                nBhi[h] = *(const uint4*)(Whi + gb);
                if (USE_BLO) nBlo[h] = *(const uint4*)(Wlo + gb);
            }
        }

        // ---- compute current chunk: 4 k-steps of 16 ----
        const uint32_t stg = sb + (c & 1) * SM_STAGE;
        #pragma unroll
        for (int kk = 0; kk < 4; kk++) {
            uint32_t ah[2][4], bh[8][2], bl[8][2];
            #pragma unroll
            for (int i = 0; i < 2; i++)
                ldsm_x4(ah[i], stg + aAddr0 + i * 16 * A_STRIDE + kk * 32);
            #pragma unroll
            for (int jj = 0; jj < 4; jj++) {
                uint32_t t[4];
                const uint32_t boff = bAddr0 + kk * 16 * B_STRIDE + jj * 32;
                ldsm_x4_trans(t, stg + SM_BHI + boff);
                bh[jj * 2][0] = t[0]; bh[jj * 2][1] = t[1];
                bh[jj * 2 + 1][0] = t[2]; bh[jj * 2 + 1][1] = t[3];
                if (USE_BLO) {
                    ldsm_x4_trans(t, stg + SM_BLO + boff);
                    bl[jj * 2][0] = t[0]; bl[jj * 2][1] = t[1];
                    bl[jj * 2 + 1][0] = t[2]; bl[jj * 2 + 1][1] = t[3];
                }
            }
            #pragma unroll
            for (int i = 0; i < 2; i++)
                #pragma unroll
                for (int j = 0; j < 8; j++) {
                    mma_f16(acc[i][j], ah[i], bh[j]);
                    if (USE_BLO) mma_f16(acc[i][j], ah[i], bl[j]);
                }
        }

        // ---- store prefetched chunk into the other stage ----
        if (c + 1 < NCHUNK) {
            char* dst = smem + ((c + 1) & 1) * SM_STAGE;
            #pragma unroll
            for (int h = 0; h < 4; h++) {
                const int row = ar + h * 32;
                *(uint4*)(dst + row * A_STRIDE + au * 16) = nA[h];
            }
            #pragma unroll
            for (int h = 0; h < 4; h++) {
                const int row = br + h * 16;
                *(uint4*)(dst + SM_BHI + row * B_STRIDE + bu * 16) = nBhi[h];
                if (USE_BLO)
                    *(uint4*)(dst + SM_BLO + row * B_STRIDE + bu * 16) = nBlo[h];
            }
        }
        __syncthreads();
    }

    // ---- epilogue ----
    #pragma unroll
    for (int i = 0; i < 2; i++) {
        const int r0 = bm + wm + i * 16 + (lane >> 2);
        #pragma unroll
        for (int j = 0; j < 8; j++) {
            const int col = bn + wn + j * 8 + (lane & 3) * 2;
            const float bx = bias[col], by = bias[col + 1];
            if (!USE_BLO) {
                const int h = col >> 6;
                const int d = col & 63;
                #pragma unroll
                for (int half = 0; half < 2; half++) {
                    const int m  = r0 + half * 8;
                    const int bi = m >> 11;
                    const int tt = m & (T_ - 1);
                    float v0 = acc[i][j][half * 2] + bx;
                    float v1 = acc[i][j][half * 2 + 1] + by;
                    const size_t idx = (((size_t)bi * H_ + h) * T_ + tt) * D_ + d;
                    if (z == 0) {
                        *(uint32_t*)(g_Qh + idx) = pack_f16x2(v0 * QSCALE, v1 * QSCALE);
                    } else {
                        __half* hiA = (z == 1) ? g_Kh : g_Vh;
                        __half* loA = (z == 1) ? g_Kl : g_Vl;
                        uint32_t uhi = pack_f16x2(v0, v1);
                        *(uint32_t*)(hiA + idx) = uhi;
                        *(uint32_t*)(loA + idx) = residual_pack_f16(uhi, v0, v1);
                    }
                }
            } else {
                #pragma unroll
                for (int half = 0; half < 2; half++) {
                    const int m = r0 + half * 8;
                    float2 v = make_float2(acc[i][j][half * 2] + bx,
                                           acc[i][j][half * 2 + 1] + by);
                    *(float2*)(out_final + (size_t)m * C_ + col) = v;
                }
            }
        }
    }
}

// ---------------------------------------------------------------------------
// Flash attention on mma.sync, fp16 2-term (exact R12 body — measured best).
// 128-thread CTAs (4 warps, 64 q-rows), 2 CTAs/SM, 2-stage cp.async K/V ring.
// ---------------------------------------------------------------------------
#define FSTR     144             // 72 f16 row stride (odd 16B multiple)
#define FS_KV    9216            // Q hi: 64*144 = 9216 @ 0; stages follow
#define FS_KLO_O 9216
#define FS_VHI_O 18432
#define FS_VLO_O 27648
#define FS_STAGE 36864
#define FS_TOTAL (FS_KV + 2 * FS_STAGE)   // 82944

__global__ __launch_bounds__(128, 2)
void flash_mma_kernel()
{
    extern __shared__ char smem[];
    const uint32_t sb = smem_u32(smem);
    const int tid  = threadIdx.x;
    const int lane = tid & 31;
    const int w    = tid >> 5;                               // 0..3
    const int qt   = (int)gridDim.x - 1 - (int)blockIdx.x;   // big tiles first
    const int bh   = blockIdx.y;
    const int q0   = qt * 64;
    const int nch  = qt + 1;                                 // 64-key chunks

    const size_t headoff = (size_t)bh * T_ * D_;
    const __half* Kh = g_Kh + headoff;
    const __half* Kl = g_Kl + headoff;
    const __half* Vh = g_Vh + headoff;
    const __half* Vl = g_Vl + headoff;

    auto issue_kv = [&](int kt, uint32_t stg) {
        #pragma unroll
        for (int i = 0; i < 4; i++) {
            const int e = tid + i * 128;     // 0..511
            const int row = e >> 3, u = e & 7;
            const size_t g = (size_t)(kt + row) * D_ + u * 8;
            const uint32_t o = (uint32_t)(row * FSTR + u * 16);
            CP_ASYNC16(stg + o,            Kh + g);
            CP_ASYNC16(stg + FS_KLO_O + o, Kl + g);
            CP_ASYNC16(stg + FS_VHI_O + o, Vh + g);
            CP_ASYNC16(stg + FS_VLO_O + o, Vl + g);
        }
    };

    issue_kv(0, sb + FS_KV);
    CP_COMMIT();

    // ---- stage Q tile (64 x 64, hi only) ----
    {
        const __half* Qh = g_Qh + headoff + (size_t)q0 * D_;
        #pragma unroll
        for (int i = 0; i < 4; i++) {
            const int e = tid + i * 128;
            const int row = e >> 3, u = e & 7;
            *(uint4*)(smem + row * FSTR + u * 16) = *(const uint4*)(Qh + row * 64 + u * 8);
        }
    }
    __syncthreads();

    // ---- Q fragments (registers for the whole loop) ----
    uint32_t qh[4][4];
    {
        const uint32_t qa = sb + (uint32_t)((16 * w + (lane & 15)) * FSTR + (lane >> 4) * 16);
        #pragma unroll
        for (int s = 0; s < 4; s++) ldsm_x4(qh[s], qa + s * 32);
    }

    float O[8][4];
    #pragma unroll
    for (int j = 0; j < 8; j++)
        #pragma unroll
        for (int r = 0; r < 4; r++) O[j][r] = 0.f;
    float m0 = -1e30f, m1 = -1e30f, l0 = 0.f, l1 = 0.f;

    const int wrow = q0 + 16 * w;
    const int r0g  = wrow + (lane >> 2);
    const int r1g  = r0g + 8;

    for (int c = 0; c < nch; ++c) {
        if (c + 1 < nch) {
            issue_kv((c + 1) * 64, sb + FS_KV + ((c + 1) & 1) * FS_STAGE);
            CP_COMMIT();
            CP_WAIT(1);
        } else {
            CP_WAIT(0);
        }
        __syncthreads();

        const int kt = c * 64;
        if (kt <= wrow + 15) {
            const uint32_t kbase = sb + FS_KV + (c & 1) * FS_STAGE;
            const int kmax = wrow + 15 - kt;

            // ---- S = qh * (kh + kl), s-outer ----
            float S[8][4];
            #pragma unroll
            for (int j = 0; j < 8; j++)
                #pragma unroll
                for (int r = 0; r < 4; r++) S[j][r] = 0.f;

            #pragma unroll
            for (int s = 0; s < 4; s++) {
                uint32_t kh[4][4], kl[4][4];
                #pragma unroll
                for (int kp = 0; kp < 4; kp++) {
                    if (kp * 16 > kmax) continue;
                    const uint32_t ka = kbase
                        + (uint32_t)((kp * 16 + (lane & 15)) * FSTR + (lane >> 4) * 16)
                        + s * 32;
                    ldsm_x4(kh[kp], ka);
                    ldsm_x4(kl[kp], ka + FS_KLO_O);
                }
                #pragma unroll
                for (int kp = 0; kp < 4; kp++) {
                    if (kp * 16 > kmax) continue;
                    uint32_t be[2] = {kh[kp][0], kh[kp][2]}, bo[2] = {kh[kp][1], kh[kp][3]};
                    uint32_t le[2] = {kl[kp][0], kl[kp][2]}, lo_[2] = {kl[kp][1], kl[kp][3]};
                    mma_f16(S[2 * kp],     qh[s], be);
                    mma_f16(S[2 * kp + 1], qh[s], bo);
                    mma_f16(S[2 * kp],     qh[s], le);
                    mma_f16(S[2 * kp + 1], qh[s], lo_);
                }
            }

            // ---- causal mask ----
            if (kt + 63 > wrow) {
                #pragma unroll
                for (int j = 0; j < 8; j++) {
                    const int c0 = kt + j * 8 + (lane & 3) * 2;
                    if (c0 > r0g)     S[j][0] = -1e30f;
                    if (c0 + 1 > r0g) S[j][1] = -1e30f;
                    if (c0 > r1g)     S[j][2] = -1e30f;
                    if (c0 + 1 > r1g) S[j][3] = -1e30f;
                }
            }

            // ---- online softmax (base-2; scale folded into Q; raw EX2) ----
            float vmax0 = -1e30f, vmax1 = -1e30f;
            #pragma unroll
            for (int j = 0; j < 8; j++) {
                vmax0 = fmaxf(vmax0, fmaxf(S[j][0], S[j][1]));
                vmax1 = fmaxf(vmax1, fmaxf(S[j][2], S[j][3]));
            }
            vmax0 = fmaxf(vmax0, __shfl_xor_sync(0xffffffffu, vmax0, 1));
            vmax0 = fmaxf(vmax0, __shfl_xor_sync(0xffffffffu, vmax0, 2));
            vmax1 = fmaxf(vmax1, __shfl_xor_sync(0xffffffffu, vmax1, 1));
            vmax1 = fmaxf(vmax1, __shfl_xor_sync(0xffffffffu, vmax1, 2));

            const float mn0 = fmaxf(m0, vmax0);
            const float mn1 = fmaxf(m1, vmax1);
            const float c0f = ex2(m0 - mn0);
            const float c1f = ex2(m1 - mn1);
            m0 = mn0; m1 = mn1;

            float sum0 = 0.f, sum1 = 0.f;
            float P[8][4];
            #pragma unroll
            for (int j = 0; j < 8; j++) {
                P[j][0] = ex2(S[j][0] - mn0);
                P[j][1] = ex2(S[j][1] - mn0);
                P[j][2] = ex2(S[j][2] - mn1);
                P[j][3] = ex2(S[j][3] - mn1);
                sum0 += P[j][0] + P[j][1];
                sum1 += P[j][2] + P[j][3];
            }
            sum0 += __shfl_xor_sync(0xffffffffu, sum0, 1);
            sum0 += __shfl_xor_sync(0xffffffffu, sum0, 2);
            sum1 += __shfl_xor_sync(0xffffffffu, sum1, 1);
            sum1 += __shfl_xor_sync(0xffffffffu, sum1, 2);
            l0 = l0 * c0f + sum0;
            l1 = l1 * c1f + sum1;

            #pragma unroll
            for (int j = 0; j < 8; j++) {
                O[j][0] *= c0f; O[j][1] *= c0f;
                O[j][2] *= c1f; O[j][3] *= c1f;
            }

            // ---- P fragments (hi only) ----
            uint32_t pa[4][4];
            #pragma unroll
            for (int kp = 0; kp < 4; kp++) {
                if (kp * 16 > kmax) continue;
                pa[kp][0] = pack_f16x2(P[2 * kp][0],     P[2 * kp][1]);
                pa[kp][1] = pack_f16x2(P[2 * kp][2],     P[2 * kp][3]);
                pa[kp][2] = pack_f16x2(P[2 * kp + 1][0], P[2 * kp + 1][1]);
                pa[kp][3] = pack_f16x2(P[2 * kp + 1][2], P[2 * kp + 1][3]);
            }

            // ---- O += P * (vh + vl) ----
            #pragma unroll
            for (int kp = 0; kp < 4; kp++) {
                if (kp * 16 > kmax) continue;
                const uint32_t va0 = kbase + FS_VHI_O
                    + (uint32_t)((kp * 16 + (lane & 7) + ((lane >> 3) & 1) * 8) * FSTR
                                 + (lane >> 4) * 16);
                #pragma unroll
                for (int db = 0; db < 4; db++) {
                    uint32_t vh[4], vl[4];
                    ldsm_x4_trans(vh, va0 + db * 32);
                    ldsm_x4_trans(vl, va0 + db * 32 + (FS_VLO_O - FS_VHI_O));
                    uint32_t bh0[2] = {vh[0], vh[1]}, bh1[2] = {vh[2], vh[3]};
                    uint32_t bl0[2] = {vl[0], vl[1]}, bl1[2] = {vl[2], vl[3]};
                    mma_f16(O[2 * db],     pa[kp], bh0);
                    mma_f16(O[2 * db + 1], pa[kp], bh1);
                    mma_f16(O[2 * db],     pa[kp], bl0);
                    mma_f16(O[2 * db + 1], pa[kp], bl1);
                }
            }
        }
        __syncthreads();
    }

    // ---- epilogue: normalize, f16 hi only, write [B,T,C] ----
    const float inv0 = 1.f / l0;
    const float inv1 = 1.f / l1;
    const int bi = bh / H_;
    const int h  = bh % H_;
    #pragma unroll
    for (int jd = 0; jd < 8; jd++) {
        const int d0 = jd * 8 + (lane & 3) * 2;
        {
            const size_t idx = ((size_t)bi * T_ + r0g) * C_ + h * 64 + d0;
            *(uint32_t*)(g_Oh + idx) = pack_f16x2(O[jd][0] * inv0, O[jd][1] * inv0);
        }
        {
            const size_t idx = ((size_t)bi * T_ + r1g) * C_ + h * 64 + d0;
            *(uint32_t*)(g_Oh + idx) = pack_f16x2(O[jd][2] * inv1, O[jd][3] * inv1);
        }
    }
}

// ---------------------------------------------------------------------------
// Launch
// ---------------------------------------------------------------------------
extern "C" void kernel_launch(void* const* d_in, const int* in_sizes, int n_in,
                              void* d_out, int out_size)
{
    const float* x  = (const float*)d_in[0];
    const float* Wq = (const float*)d_in[1];
    const float* bq = (const float*)d_in[2];
    const float* Wk = (const float*)d_in[3];
    const float* bk = (const float*)d_in[4];
    const float* Wv = (const float*)d_in[5];
    const float* bv = (const float*)d_in[6];
    const float* Wo = (const float*)d_in[7];
    const float* bo = (const float*)d_in[8];

    static bool attr_set = false;
    if (!attr_set) {
        cudaFuncSetAttribute(tc_gemm_kernel<false>,
                             cudaFuncAttributeMaxDynamicSharedMemorySize, SM_TOTAL);
        cudaFuncSetAttribute(tc_gemm_kernel<true>,
                             cudaFuncAttributeMaxDynamicSharedMemorySize, SM_TOTAL);
        cudaFuncSetAttribute(flash_mma_kernel,
                             cudaFuncAttributeMaxDynamicSharedMemorySize, FS_TOTAL);
        attr_set = true;
    }

    cvt_x_kernel<<<(M_ * C_) / 1024, 1024>>>(x);
    cvt_w_kernel<<<dim3((C_ * C_) / 1024, 4), 1024>>>(Wq, Wk, Wv, Wo);

    tc_gemm_kernel<false><<<dim3(C_ / 128, M_ / 128, 3), 256, SM_TOTAL>>>(
        nullptr, bq, bk, bv);

    flash_mma_kernel<<<dim3(T_ / 64, B_ * H_), 128, FS_TOTAL>>>();

    tc_gemm_kernel<true><<<dim3(C_ / 128, M_ / 128, 1), 256, SM_TOTAL>>>(
        (float*)d_out, bo, nullptr, nullptr);
}

// round 15
// speedup vs baseline: 2.0739x; 1.3658x over previous
#include <cuda_runtime.h>
#include <cuda_fp16.h>
#include <cstdint>

// ---------------------------------------------------------------------------
// Problem constants
// ---------------------------------------------------------------------------
#define B_  4
#define T_  2048
#define C_  768
#define H_  12
#define D_  64
#define M_  (B_ * T_)          // 8192
#define QSCALE (0.125f * 1.4426950408889634f)   // 1/sqrt(64) * log2(e)

// ---------------------------------------------------------------------------
// Scratch device globals.  fp16 scheme (error-budgeted):
//   QKV proj:  acc = f16(x) * f16(W)            (1-term)
//   flash:     S = qh*kh,  O += f16(P)*vh       (1-term)
//   out proj:  acc = f16(O) * (Wo_hi + Wo_lo)   (2-term)
// ---------------------------------------------------------------------------
__device__ __half g_Xh[(size_t)M_ * C_];                 // x, hi only
__device__ __half g_Whi[4 * (size_t)C_ * C_];            // Wq,Wk,Wv,Wo hi
__device__ __half g_Wlo[(size_t)C_ * C_];                // Wo lo only

__device__ __half g_Qh[(size_t)B_ * H_ * T_ * D_];       // Q hi (pre-scaled)
__device__ __half g_Kh[(size_t)B_ * H_ * T_ * D_];       // K hi
__device__ __half g_Vh[(size_t)B_ * H_ * T_ * D_];       // V hi

__device__ __half g_Oh[(size_t)M_ * C_];                 // attn out, hi only

// ---------------------------------------------------------------------------
// PTX helpers
// ---------------------------------------------------------------------------
__device__ __forceinline__ uint32_t smem_u32(const void* p) {
    uint32_t a;
    asm("{ .reg .u64 t; cvta.to.shared.u64 t, %1; cvt.u32.u64 %0, t; }"
        : "=r"(a) : "l"(p));
    return a;
}

#define CP_ASYNC16(dst, src) \
    asm volatile("cp.async.cg.shared.global [%0], [%1], 16;" \
                 :: "r"(dst), "l"(src) : "memory")
#define CP_COMMIT() asm volatile("cp.async.commit_group;" ::: "memory")
#define CP_WAIT(n)  asm volatile("cp.async.wait_group %0;" :: "n"(n) : "memory")

__device__ __forceinline__ void ldsm_x4(uint32_t* r, uint32_t addr) {
    asm volatile("ldmatrix.sync.aligned.m8n8.x4.shared.b16 {%0,%1,%2,%3}, [%4];"
                 : "=r"(r[0]), "=r"(r[1]), "=r"(r[2]), "=r"(r[3]) : "r"(addr));
}

__device__ __forceinline__ void ldsm_x4_trans(uint32_t* r, uint32_t addr) {
    asm volatile("ldmatrix.sync.aligned.m8n8.x4.trans.shared.b16 {%0,%1,%2,%3}, [%4];"
                 : "=r"(r[0]), "=r"(r[1]), "=r"(r[2]), "=r"(r[3]) : "r"(addr));
}

__device__ __forceinline__ void mma_f16(float* c, const uint32_t* a, const uint32_t* b) {
    asm volatile(
        "mma.sync.aligned.m16n8k16.row.col.f32.f16.f16.f32 "
        "{%0,%1,%2,%3}, {%4,%5,%6,%7}, {%8,%9}, {%0,%1,%2,%3};"
        : "+f"(c[0]), "+f"(c[1]), "+f"(c[2]), "+f"(c[3])
        : "r"(a[0]), "r"(a[1]), "r"(a[2]), "r"(a[3]), "r"(b[0]), "r"(b[1]));
}

__device__ __forceinline__ float ex2(float x) {          // raw MUFU.EX2
    float y;
    asm("ex2.approx.f32 %0, %1;" : "=f"(y) : "f"(x));
    return y;
}

__device__ __forceinline__ uint32_t pack_f16x2(float lo, float hi) {
    uint32_t r;
    asm("cvt.rn.f16x2.f32 %0, %1, %2;" : "=r"(r) : "f"(hi), "f"(lo));
    return r;
}

// ---------------------------------------------------------------------------
// Converters
// ---------------------------------------------------------------------------
__global__ void cvt_x_kernel(const float* __restrict__ src) {
    size_t i = (size_t)blockIdx.x * blockDim.x + threadIdx.x;
    g_Xh[i] = __float2half(src[i]);
}

__global__ void cvt_w_kernel(const float* __restrict__ Wq, const float* __restrict__ Wk,
                             const float* __restrict__ Wv, const float* __restrict__ Wo) {
    const float* src = (blockIdx.y == 0) ? Wq : (blockIdx.y == 1) ? Wk
                      : (blockIdx.y == 2) ? Wv : Wo;
    size_t off = (size_t)blockIdx.y * C_ * C_;
    size_t i = (size_t)blockIdx.x * blockDim.x + threadIdx.x;
    float v = src[i];
    __half h = __float2half(v);
    g_Whi[off + i] = h;
    if (blockIdx.y == 3)                      // lo kept only for Wo
        g_Wlo[i] = __float2half(v - __half2float(h));
}

// ---------------------------------------------------------------------------
// GEMM via mma.sync.  BK=64 (12 chunks), CTA 128x128, 256 threads,
// double-buffered, register-staged prefetch.  USE_BLO compile-time:
// QKV proj = lean 1-term body, out proj = 2-term.
// ---------------------------------------------------------------------------
#define BK      64
#define NCHUNK  (C_ / BK)      // 12
#define A_STRIDE 144           // 64 f16 + 8 pad -> 9 x 16B, conflict-free
#define B_STRIDE 272           // 128 f16 + 8 pad -> 17 x 16B
#define SM_BHI   18432         // after A hi: 128*144
#define SM_BLO   35840         // + 64*272
#define SM_STAGE 53248
#define SM_TOTAL (2 * SM_STAGE)   // 106496

template<bool USE_BLO>
__global__ __launch_bounds__(256, 1)
void tc_gemm_kernel(float* __restrict__ out_final,
                    const float* __restrict__ b0, const float* __restrict__ b1,
                    const float* __restrict__ b2)
{
    extern __shared__ char smem[];
    const uint32_t sb = smem_u32(smem);
    const int tid  = threadIdx.x;
    const int lane = tid & 31;
    const int w    = tid >> 5;
    const int wm   = (w & 3) * 32;
    const int wn   = (w >> 2) * 64;

    const int z    = blockIdx.z;
    const int widx = USE_BLO ? 3 : z;
    const __half* Ah  = USE_BLO ? g_Oh : g_Xh;
    const __half* Whi = g_Whi + (size_t)widx * C_ * C_;
    const __half* Wlo = g_Wlo;
    const float* bias = USE_BLO ? b0 : ((z == 0) ? b0 : (z == 1) ? b1 : b2);

    const int bm = blockIdx.y * 128;
    const int bn = blockIdx.x * 128;

    float acc[2][8][4];
    #pragma unroll
    for (int i = 0; i < 2; i++)
        #pragma unroll
        for (int j = 0; j < 8; j++)
            #pragma unroll
            for (int r = 0; r < 4; r++) acc[i][j][r] = 0.f;

    const int au = tid & 7;
    const int ar = tid >> 3;
    const int bu = tid & 15;
    const int br = tid >> 4;

    const uint32_t aAddr0 = (uint32_t)((wm + (lane & 15)) * A_STRIDE + (lane >> 4) * 16);
    const uint32_t bAddr0 = (uint32_t)(((lane & 7) + ((lane >> 3) & 1) * 8) * B_STRIDE
                                       + (wn + (lane >> 4) * 8) * 2);

    // ---- prologue: chunk 0 into stage 0 ----
    {
        #pragma unroll
        for (int h = 0; h < 4; h++) {
            const int row = ar + h * 32;
            *(uint4*)(smem + row * A_STRIDE + au * 16) =
                *(const uint4*)(Ah + (size_t)(bm + row) * C_ + au * 8);
        }
        #pragma unroll
        for (int h = 0; h < 4; h++) {
            const int row = br + h * 16;
            const size_t gb = (size_t)row * C_ + bn + bu * 8;
            *(uint4*)(smem + SM_BHI + row * B_STRIDE + bu * 16) = *(const uint4*)(Whi + gb);
            if (USE_BLO)
                *(uint4*)(smem + SM_BLO + row * B_STRIDE + bu * 16) = *(const uint4*)(Wlo + gb);
        }
    }
    __syncthreads();

    for (int c = 0; c < NCHUNK; ++c) {
        // ---- register-staged prefetch of next chunk ----
        uint4 nA[4], nBhi[4], nBlo[4];
        if (c + 1 < NCHUNK) {
            const int k0 = (c + 1) * BK;
            #pragma unroll
            for (int h = 0; h < 4; h++) {
                const int row = ar + h * 32;
                nA[h] = *(const uint4*)(Ah + (size_t)(bm + row) * C_ + k0 + au * 8);
            }
            #pragma unroll
            for (int h = 0; h < 4; h++) {
                const int row = br + h * 16;
                const size_t gb = (size_t)(k0 + row) * C_ + bn + bu * 8;
                nBhi[h] = *(const uint4*)(Whi + gb);
                if (USE_BLO) nBlo[h] = *(const uint4*)(Wlo + gb);
            }
        }

        // ---- compute current chunk: 4 k-steps of 16 ----
        const uint32_t stg = sb + (c & 1) * SM_STAGE;
        #pragma unroll
        for (int kk = 0; kk < 4; kk++) {
            uint32_t ah[2][4], bh[8][2], bl[8][2];
            #pragma unroll
            for (int i = 0; i < 2; i++)
                ldsm_x4(ah[i], stg + aAddr0 + i * 16 * A_STRIDE + kk * 32);
            #pragma unroll
            for (int jj = 0; jj < 4; jj++) {
                uint32_t t[4];
                const uint32_t boff = bAddr0 + kk * 16 * B_STRIDE + jj * 32;
                ldsm_x4_trans(t, stg + SM_BHI + boff);
                bh[jj * 2][0] = t[0]; bh[jj * 2][1] = t[1];
                bh[jj * 2 + 1][0] = t[2]; bh[jj * 2 + 1][1] = t[3];
                if (USE_BLO) {
                    ldsm_x4_trans(t, stg + SM_BLO + boff);
                    bl[jj * 2][0] = t[0]; bl[jj * 2][1] = t[1];
                    bl[jj * 2 + 1][0] = t[2]; bl[jj * 2 + 1][1] = t[3];
                }
            }
            #pragma unroll
            for (int i = 0; i < 2; i++)
                #pragma unroll
                for (int j = 0; j < 8; j++) {
                    mma_f16(acc[i][j], ah[i], bh[j]);
                    if (USE_BLO) mma_f16(acc[i][j], ah[i], bl[j]);
                }
        }

        // ---- store prefetched chunk into the other stage ----
        if (c + 1 < NCHUNK) {
            char* dst = smem + ((c + 1) & 1) * SM_STAGE;
            #pragma unroll
            for (int h = 0; h < 4; h++) {
                const int row = ar + h * 32;
                *(uint4*)(dst + row * A_STRIDE + au * 16) = nA[h];
            }
            #pragma unroll
            for (int h = 0; h < 4; h++) {
                const int row = br + h * 16;
                *(uint4*)(dst + SM_BHI + row * B_STRIDE + bu * 16) = nBhi[h];
                if (USE_BLO)
                    *(uint4*)(dst + SM_BLO + row * B_STRIDE + bu * 16) = nBlo[h];
            }
        }
        __syncthreads();
    }

    // ---- epilogue ----
    #pragma unroll
    for (int i = 0; i < 2; i++) {
        const int r0 = bm + wm + i * 16 + (lane >> 2);
        #pragma unroll
        for (int j = 0; j < 8; j++) {
            const int col = bn + wn + j * 8 + (lane & 3) * 2;
            const float bx = bias[col], by = bias[col + 1];
            if (!USE_BLO) {
                const int h = col >> 6;
                const int d = col & 63;
                __half* dstA = (z == 0) ? g_Qh : (z == 1) ? g_Kh : g_Vh;
                const float sc = (z == 0) ? QSCALE : 1.f;
                #pragma unroll
                for (int half = 0; half < 2; half++) {
                    const int m  = r0 + half * 8;
                    const int bi = m >> 11;
                    const int tt = m & (T_ - 1);
                    const float v0 = (acc[i][j][half * 2] + bx) * sc;
                    const float v1 = (acc[i][j][half * 2 + 1] + by) * sc;
                    const size_t idx = (((size_t)bi * H_ + h) * T_ + tt) * D_ + d;
                    *(uint32_t*)(dstA + idx) = pack_f16x2(v0, v1);
                }
            } else {
                #pragma unroll
                for (int half = 0; half < 2; half++) {
                    const int m = r0 + half * 8;
                    float2 v = make_float2(acc[i][j][half * 2] + bx,
                                           acc[i][j][half * 2 + 1] + by);
                    *(float2*)(out_final + (size_t)m * C_ + col) = v;
                }
            }
        }
    }
}

// ---------------------------------------------------------------------------
// Flash attention on mma.sync, fp16 1-term: S = qh*kh, O += f16(P)*vh.
// 128-thread CTAs (4 warps, 64 q-rows), 2 CTAs/SM, 2-stage cp.async K/V ring.
// ---------------------------------------------------------------------------
#define FSTR     144             // 72 f16 row stride (odd 16B multiple)
#define FS_KV    9216            // Q hi: 64*144 @ 0; stages follow
#define FS_V_O   9216            // V offset within a stage
#define FS_STAGE 18432           // K (9216) + V (9216)
#define FS_TOTAL (FS_KV + 2 * FS_STAGE)   // 46080

__global__ __launch_bounds__(128, 2)
void flash_mma_kernel()
{
    extern __shared__ char smem[];
    const uint32_t sb = smem_u32(smem);
    const int tid  = threadIdx.x;
    const int lane = tid & 31;
    const int w    = tid >> 5;                               // 0..3
    const int qt   = (int)gridDim.x - 1 - (int)blockIdx.x;   // big tiles first
    const int bh   = blockIdx.y;
    const int q0   = qt * 64;
    const int nch  = qt + 1;                                 // 64-key chunks

    const size_t headoff = (size_t)bh * T_ * D_;
    const __half* Kh = g_Kh + headoff;
    const __half* Vh = g_Vh + headoff;

    auto issue_kv = [&](int kt, uint32_t stg) {
        #pragma unroll
        for (int i = 0; i < 4; i++) {
            const int e = tid + i * 128;     // 0..511
            const int row = e >> 3, u = e & 7;
            const size_t g = (size_t)(kt + row) * D_ + u * 8;
            const uint32_t o = (uint32_t)(row * FSTR + u * 16);
            CP_ASYNC16(stg + o,          Kh + g);
            CP_ASYNC16(stg + FS_V_O + o, Vh + g);
        }
    };

    issue_kv(0, sb + FS_KV);
    CP_COMMIT();

    // ---- stage Q tile (64 x 64, hi only) ----
    {
        const __half* Qh = g_Qh + headoff + (size_t)q0 * D_;
        #pragma unroll
        for (int i = 0; i < 4; i++) {
            const int e = tid + i * 128;
            const int row = e >> 3, u = e & 7;
            *(uint4*)(smem + row * FSTR + u * 16) = *(const uint4*)(Qh + row * 64 + u * 8);
        }
    }
    __syncthreads();

    // ---- Q fragments (registers for the whole loop) ----
    uint32_t qh[4][4];
    {
        const uint32_t qa = sb + (uint32_t)((16 * w + (lane & 15)) * FSTR + (lane >> 4) * 16);
        #pragma unroll
        for (int s = 0; s < 4; s++) ldsm_x4(qh[s], qa + s * 32);
    }

    float O[8][4];
    #pragma unroll
    for (int j = 0; j < 8; j++)
        #pragma unroll
        for (int r = 0; r < 4; r++) O[j][r] = 0.f;
    float m0 = -1e30f, m1 = -1e30f, l0 = 0.f, l1 = 0.f;

    const int wrow = q0 + 16 * w;
    const int r0g  = wrow + (lane >> 2);
    const int r1g  = r0g + 8;

    for (int c = 0; c < nch; ++c) {
        if (c + 1 < nch) {
            issue_kv((c + 1) * 64, sb + FS_KV + ((c + 1) & 1) * FS_STAGE);
            CP_COMMIT();
            CP_WAIT(1);
        } else {
            CP_WAIT(0);
        }
        __syncthreads();

        const int kt = c * 64;
        if (kt <= wrow + 15) {
            const uint32_t kbase = sb + FS_KV + (c & 1) * FS_STAGE;
            const int kmax = wrow + 15 - kt;

            // ---- S = qh * kh, s-outer ----
            float S[8][4];
            #pragma unroll
            for (int j = 0; j < 8; j++)
                #pragma unroll
                for (int r = 0; r < 4; r++) S[j][r] = 0.f;

            #pragma unroll
            for (int s = 0; s < 4; s++) {
                uint32_t kh[4][4];
                #pragma unroll
                for (int kp = 0; kp < 4; kp++) {
                    if (kp * 16 > kmax) continue;
                    const uint32_t ka = kbase
                        + (uint32_t)((kp * 16 + (lane & 15)) * FSTR + (lane >> 4) * 16)
                        + s * 32;
                    ldsm_x4(kh[kp], ka);
                }
                #pragma unroll
                for (int kp = 0; kp < 4; kp++) {
                    if (kp * 16 > kmax) continue;
                    uint32_t be[2] = {kh[kp][0], kh[kp][2]}, bo[2] = {kh[kp][1], kh[kp][3]};
                    mma_f16(S[2 * kp],     qh[s], be);
                    mma_f16(S[2 * kp + 1], qh[s], bo);
                }
            }

            // ---- causal mask ----
            if (kt + 63 > wrow) {
                #pragma unroll
                for (int j = 0; j < 8; j++) {
                    const int c0 = kt + j * 8 + (lane & 3) * 2;
                    if (c0 > r0g)     S[j][0] = -1e30f;
                    if (c0 + 1 > r0g) S[j][1] = -1e30f;
                    if (c0 > r1g)     S[j][2] = -1e30f;
                    if (c0 + 1 > r1g) S[j][3] = -1e30f;
                }
            }

            // ---- online softmax (base-2; scale folded into Q; raw EX2) ----
            float vmax0 = -1e30f, vmax1 = -1e30f;
            #pragma unroll
            for (int j = 0; j < 8; j++) {
                vmax0 = fmaxf(vmax0, fmaxf(S[j][0], S[j][1]));
                vmax1 = fmaxf(vmax1, fmaxf(S[j][2], S[j][3]));
            }
            vmax0 = fmaxf(vmax0, __shfl_xor_sync(0xffffffffu, vmax0, 1));
            vmax0 = fmaxf(vmax0, __shfl_xor_sync(0xffffffffu, vmax0, 2));
            vmax1 = fmaxf(vmax1, __shfl_xor_sync(0xffffffffu, vmax1, 1));
            vmax1 = fmaxf(vmax1, __shfl_xor_sync(0xffffffffu, vmax1, 2));

            const float mn0 = fmaxf(m0, vmax0);
            const float mn1 = fmaxf(m1, vmax1);
            const float c0f = ex2(m0 - mn0);
            const float c1f = ex2(m1 - mn1);
            m0 = mn0; m1 = mn1;

            float sum0 = 0.f, sum1 = 0.f;
            float P[8][4];
            #pragma unroll
            for (int j = 0; j < 8; j++) {
                P[j][0] = ex2(S[j][0] - mn0);
                P[j][1] = ex2(S[j][1] - mn0);
                P[j][2] = ex2(S[j][2] - mn1);
                P[j][3] = ex2(S[j][3] - mn1);
                sum0 += P[j][0] + P[j][1];
                sum1 += P[j][2] + P[j][3];
            }
            sum0 += __shfl_xor_sync(0xffffffffu, sum0, 1);
            sum0 += __shfl_xor_sync(0xffffffffu, sum0, 2);
            sum1 += __shfl_xor_sync(0xffffffffu, sum1, 1);
            sum1 += __shfl_xor_sync(0xffffffffu, sum1, 2);
            l0 = l0 * c0f + sum0;
            l1 = l1 * c1f + sum1;

            #pragma unroll
            for (int j = 0; j < 8; j++) {
                O[j][0] *= c0f; O[j][1] *= c0f;
                O[j][2] *= c1f; O[j][3] *= c1f;
            }

            // ---- P fragments (hi only) ----
            uint32_t pa[4][4];
            #pragma unroll
            for (int kp = 0; kp < 4; kp++) {
                if (kp * 16 > kmax) continue;
                pa[kp][0] = pack_f16x2(P[2 * kp][0],     P[2 * kp][1]);
                pa[kp][1] = pack_f16x2(P[2 * kp][2],     P[2 * kp][3]);
                pa[kp][2] = pack_f16x2(P[2 * kp + 1][0], P[2 * kp + 1][1]);
                pa[kp][3] = pack_f16x2(P[2 * kp + 1][2], P[2 * kp + 1][3]);
            }

            // ---- O += P * vh ----
            #pragma unroll
            for (int kp = 0; kp < 4; kp++) {
                if (kp * 16 > kmax) continue;
                const uint32_t va0 = kbase + FS_V_O
                    + (uint32_t)((kp * 16 + (lane & 7) + ((lane >> 3) & 1) * 8) * FSTR
                                 + (lane >> 4) * 16);
                #pragma unroll
                for (int db = 0; db < 4; db++) {
                    uint32_t vh[4];
                    ldsm_x4_trans(vh, va0 + db * 32);
                    uint32_t bh0[2] = {vh[0], vh[1]}, bh1[2] = {vh[2], vh[3]};
                    mma_f16(O[2 * db],     pa[kp], bh0);
                    mma_f16(O[2 * db + 1], pa[kp], bh1);
                }
            }
        }
        __syncthreads();
    }

    // ---- epilogue: normalize, f16 hi only, write [B,T,C] ----
    const float inv0 = 1.f / l0;
    const float inv1 = 1.f / l1;
    const int bi = bh / H_;
    const int h  = bh % H_;
    #pragma unroll
    for (int jd = 0; jd < 8; jd++) {
        const int d0 = jd * 8 + (lane & 3) * 2;
        {
            const size_t idx = ((size_t)bi * T_ + r0g) * C_ + h * 64 + d0;
            *(uint32_t*)(g_Oh + idx) = pack_f16x2(O[jd][0] * inv0, O[jd][1] * inv0);
        }
        {
            const size_t idx = ((size_t)bi * T_ + r1g) * C_ + h * 64 + d0;
            *(uint32_t*)(g_Oh + idx) = pack_f16x2(O[jd][2] * inv1, O[jd][3] * inv1);
        }
    }
}

// ---------------------------------------------------------------------------
// Launch
// ---------------------------------------------------------------------------
extern "C" void kernel_launch(void* const* d_in, const int* in_sizes, int n_in,
                              void* d_out, int out_size)
{
    const float* x  = (const float*)d_in[0];
    const float* Wq = (const float*)d_in[1];
    const float* bq = (const float*)d_in[2];
    const float* Wk = (const float*)d_in[3];
    const float* bk = (const float*)d_in[4];
    const float* Wv = (const float*)d_in[5];
    const float* bv = (const float*)d_in[6];
    const float* Wo = (const float*)d_in[7];
    const float* bo = (const float*)d_in[8];

    static bool attr_set = false;
    if (!attr_set) {
        cudaFuncSetAttribute(tc_gemm_kernel<false>,
                             cudaFuncAttributeMaxDynamicSharedMemorySize, SM_TOTAL);
        cudaFuncSetAttribute(tc_gemm_kernel<true>,
                             cudaFuncAttributeMaxDynamicSharedMemorySize, SM_TOTAL);
        cudaFuncSetAttribute(flash_mma_kernel,
                             cudaFuncAttributeMaxDynamicSharedMemorySize, FS_TOTAL);
        attr_set = true;
    }

    cvt_x_kernel<<<(M_ * C_) / 1024, 1024>>>(x);
    cvt_w_kernel<<<dim3((C_ * C_) / 1024, 4), 1024>>>(Wq, Wk, Wv, Wo);

    tc_gemm_kernel<false><<<dim3(C_ / 128, M_ / 128, 3), 256, SM_TOTAL>>>(
        nullptr, bq, bk, bv);

    flash_mma_kernel<<<dim3(T_ / 64, B_ * H_), 128, FS_TOTAL>>>();

    tc_gemm_kernel<true><<<dim3(C_ / 128, M_ / 128, 1), 256, SM_TOTAL>>>(
        (float*)d_out, bo, nullptr, nullptr);
}

// round 17
// speedup vs baseline: 2.2164x; 1.0687x over previous
#include <cuda_runtime.h>
#include <cuda_fp16.h>
#include <cstdint>

// ---------------------------------------------------------------------------
// Problem constants
// ---------------------------------------------------------------------------
#define B_  4
#define T_  2048
#define C_  768
#define H_  12
#define D_  64
#define M_  (B_ * T_)          // 8192
#define QSCALE (0.125f * 1.4426950408889634f)   // 1/sqrt(64) * log2(e)

// ---------------------------------------------------------------------------
// Scratch device globals.  fp16 1-term everywhere (error-budgeted, measured):
//   QKV proj:  acc = f16(x) * f16(W)
//   flash:     S = qh*kh,  O += f16(P)*vh
//   out proj:  acc = f16(O) * f16(Wo)
// ---------------------------------------------------------------------------
__device__ __half g_Xh[(size_t)M_ * C_];                 // x
__device__ __half g_Whi[4 * (size_t)C_ * C_];            // Wq,Wk,Wv,Wo

__device__ __half g_Qh[(size_t)B_ * H_ * T_ * D_];       // Q (pre-scaled)
__device__ __half g_Kh[(size_t)B_ * H_ * T_ * D_];       // K
__device__ __half g_Vh[(size_t)B_ * H_ * T_ * D_];       // V

__device__ __half g_Oh[(size_t)M_ * C_];                 // attn out

// ---------------------------------------------------------------------------
// PTX helpers
// ---------------------------------------------------------------------------
__device__ __forceinline__ uint32_t smem_u32(const void* p) {
    uint32_t a;
    asm("{ .reg .u64 t; cvta.to.shared.u64 t, %1; cvt.u32.u64 %0, t; }"
        : "=r"(a) : "l"(p));
    return a;
}

#define CP_ASYNC16(dst, src) \
    asm volatile("cp.async.cg.shared.global [%0], [%1], 16;" \
                 :: "r"(dst), "l"(src) : "memory")
#define CP_COMMIT() asm volatile("cp.async.commit_group;" ::: "memory")
#define CP_WAIT(n)  asm volatile("cp.async.wait_group %0;" :: "n"(n) : "memory")

__device__ __forceinline__ void ldsm_x4(uint32_t* r, uint32_t addr) {
    asm volatile("ldmatrix.sync.aligned.m8n8.x4.shared.b16 {%0,%1,%2,%3}, [%4];"
                 : "=r"(r[0]), "=r"(r[1]), "=r"(r[2]), "=r"(r[3]) : "r"(addr));
}

__device__ __forceinline__ void ldsm_x4_trans(uint32_t* r, uint32_t addr) {
    asm volatile("ldmatrix.sync.aligned.m8n8.x4.trans.shared.b16 {%0,%1,%2,%3}, [%4];"
                 : "=r"(r[0]), "=r"(r[1]), "=r"(r[2]), "=r"(r[3]) : "r"(addr));
}

__device__ __forceinline__ void mma_f16(float* c, const uint32_t* a, const uint32_t* b) {
    asm volatile(
        "mma.sync.aligned.m16n8k16.row.col.f32.f16.f16.f32 "
        "{%0,%1,%2,%3}, {%4,%5,%6,%7}, {%8,%9}, {%0,%1,%2,%3};"
        : "+f"(c[0]), "+f"(c[1]), "+f"(c[2]), "+f"(c[3])
        : "r"(a[0]), "r"(a[1]), "r"(a[2]), "r"(a[3]), "r"(b[0]), "r"(b[1]));
}

__device__ __forceinline__ float ex2(float x) {          // raw MUFU.EX2
    float y;
    asm("ex2.approx.f32 %0, %1;" : "=f"(y) : "f"(x));
    return y;
}

__device__ __forceinline__ uint32_t pack_f16x2(float lo, float hi) {
    uint32_t r;
    asm("cvt.rn.f16x2.f32 %0, %1, %2;" : "=r"(r) : "f"(hi), "f"(lo));
    return r;
}

// ---------------------------------------------------------------------------
// Converters
// ---------------------------------------------------------------------------
__global__ void cvt_x_kernel(const float* __restrict__ src) {
    size_t i = (size_t)blockIdx.x * blockDim.x + threadIdx.x;
    g_Xh[i] = __float2half(src[i]);
}

__global__ void cvt_w_kernel(const float* __restrict__ Wq, const float* __restrict__ Wk,
                             const float* __restrict__ Wv, const float* __restrict__ Wo) {
    const float* src = (blockIdx.y == 0) ? Wq : (blockIdx.y == 1) ? Wk
                      : (blockIdx.y == 2) ? Wv : Wo;
    size_t off = (size_t)blockIdx.y * C_ * C_;
    size_t i = (size_t)blockIdx.x * blockDim.x + threadIdx.x;
    g_Whi[off + i] = __float2half(src[i]);
}

// ---------------------------------------------------------------------------
// GEMM via mma.sync, fp16 1-term.  BK=64 (12 chunks), CTA 128x128,
// 256 threads, double-buffered, register-staged prefetch.
// OUT=false: QKV proj (epilogue -> f16 Q/K/V, Q pre-scaled).
// OUT=true : out proj (epilogue -> fp32 d_out).
// ---------------------------------------------------------------------------
#define BK      64
#define NCHUNK  (C_ / BK)      // 12
#define A_STRIDE 144           // 64 f16 + 8 pad -> 9 x 16B, conflict-free
#define B_STRIDE 272           // 128 f16 + 8 pad -> 17 x 16B
#define SM_BHI   18432         // after A: 128*144
#define SM_STAGE 35840         // 18432 + 64*272
#define SM_TOTAL (2 * SM_STAGE)   // 71680

template<bool OUT>
__global__ __launch_bounds__(256, 1)
void tc_gemm_kernel(float* __restrict__ out_final,
                    const float* __restrict__ b0, const float* __restrict__ b1,
                    const float* __restrict__ b2)
{
    extern __shared__ char smem[];
    const uint32_t sb = smem_u32(smem);
    const int tid  = threadIdx.x;
    const int lane = tid & 31;
    const int w    = tid >> 5;
    const int wm   = (w & 3) * 32;
    const int wn   = (w >> 2) * 64;

    const int z    = blockIdx.z;
    const int widx = OUT ? 3 : z;
    const __half* Ah  = OUT ? g_Oh : g_Xh;
    const __half* Whi = g_Whi + (size_t)widx * C_ * C_;
    const float* bias = OUT ? b0 : ((z == 0) ? b0 : (z == 1) ? b1 : b2);

    const int bm = blockIdx.y * 128;
    const int bn = blockIdx.x * 128;

    float acc[2][8][4];
    #pragma unroll
    for (int i = 0; i < 2; i++)
        #pragma unroll
        for (int j = 0; j < 8; j++)
            #pragma unroll
            for (int r = 0; r < 4; r++) acc[i][j][r] = 0.f;

    const int au = tid & 7;
    const int ar = tid >> 3;
    const int bu = tid & 15;
    const int br = tid >> 4;

    const uint32_t aAddr0 = (uint32_t)((wm + (lane & 15)) * A_STRIDE + (lane >> 4) * 16);
    const uint32_t bAddr0 = (uint32_t)(((lane & 7) + ((lane >> 3) & 1) * 8) * B_STRIDE
                                       + (wn + (lane >> 4) * 8) * 2);

    // ---- prologue: chunk 0 into stage 0 ----
    {
        #pragma unroll
        for (int h = 0; h < 4; h++) {
            const int row = ar + h * 32;
            *(uint4*)(smem + row * A_STRIDE + au * 16) =
                *(const uint4*)(Ah + (size_t)(bm + row) * C_ + au * 8);
        }
        #pragma unroll
        for (int h = 0; h < 4; h++) {
            const int row = br + h * 16;
            *(uint4*)(smem + SM_BHI + row * B_STRIDE + bu * 16) =
                *(const uint4*)(Whi + (size_t)row * C_ + bn + bu * 8);
        }
    }
    __syncthreads();

    for (int c = 0; c < NCHUNK; ++c) {
        // ---- register-staged prefetch of next chunk ----
        uint4 nA[4], nB[4];
        if (c + 1 < NCHUNK) {
            const int k0 = (c + 1) * BK;
            #pragma unroll
            for (int h = 0; h < 4; h++) {
                const int row = ar + h * 32;
                nA[h] = *(const uint4*)(Ah + (size_t)(bm + row) * C_ + k0 + au * 8);
            }
            #pragma unroll
            for (int h = 0; h < 4; h++) {
                const int row = br + h * 16;
                nB[h] = *(const uint4*)(Whi + (size_t)(k0 + row) * C_ + bn + bu * 8);
            }
        }

        // ---- compute current chunk: 4 k-steps of 16 ----
        const uint32_t stg = sb + (c & 1) * SM_STAGE;
        #pragma unroll
        for (int kk = 0; kk < 4; kk++) {
            uint32_t ah[2][4], bh[8][2];
            #pragma unroll
            for (int i = 0; i < 2; i++)
                ldsm_x4(ah[i], stg + aAddr0 + i * 16 * A_STRIDE + kk * 32);
            #pragma unroll
            for (int jj = 0; jj < 4; jj++) {
                uint32_t t[4];
                ldsm_x4_trans(t, stg + SM_BHI + bAddr0 + kk * 16 * B_STRIDE + jj * 32);
                bh[jj * 2][0] = t[0]; bh[jj * 2][1] = t[1];
                bh[jj * 2 + 1][0] = t[2]; bh[jj * 2 + 1][1] = t[3];
            }
            #pragma unroll
            for (int i = 0; i < 2; i++)
                #pragma unroll
                for (int j = 0; j < 8; j++)
                    mma_f16(acc[i][j], ah[i], bh[j]);
        }

        // ---- store prefetched chunk into the other stage ----
        if (c + 1 < NCHUNK) {
            char* dst = smem + ((c + 1) & 1) * SM_STAGE;
            #pragma unroll
            for (int h = 0; h < 4; h++) {
                const int row = ar + h * 32;
                *(uint4*)(dst + row * A_STRIDE + au * 16) = nA[h];
            }
            #pragma unroll
            for (int h = 0; h < 4; h++) {
                const int row = br + h * 16;
                *(uint4*)(dst + SM_BHI + row * B_STRIDE + bu * 16) = nB[h];
            }
        }
        __syncthreads();
    }

    // ---- epilogue ----
    #pragma unroll
    for (int i = 0; i < 2; i++) {
        const int r0 = bm + wm + i * 16 + (lane >> 2);
        #pragma unroll
        for (int j = 0; j < 8; j++) {
            const int col = bn + wn + j * 8 + (lane & 3) * 2;
            const float bx = bias[col], by = bias[col + 1];
            if (!OUT) {
                const int h = col >> 6;
                const int d = col & 63;
                __half* dstA = (z == 0) ? g_Qh : (z == 1) ? g_Kh : g_Vh;
                const float sc = (z == 0) ? QSCALE : 1.f;
                #pragma unroll
                for (int half = 0; half < 2; half++) {
                    const int m  = r0 + half * 8;
                    const int bi = m >> 11;
                    const int tt = m & (T_ - 1);
                    const float v0 = (acc[i][j][half * 2] + bx) * sc;
                    const float v1 = (acc[i][j][half * 2 + 1] + by) * sc;
                    const size_t idx = (((size_t)bi * H_ + h) * T_ + tt) * D_ + d;
                    *(uint32_t*)(dstA + idx) = pack_f16x2(v0, v1);
                }
            } else {
                #pragma unroll
                for (int half = 0; half < 2; half++) {
                    const int m = r0 + half * 8;
                    float2 v = make_float2(acc[i][j][half * 2] + bx,
                                           acc[i][j][half * 2 + 1] + by);
                    *(float2*)(out_final + (size_t)m * C_ + col) = v;
                }
            }
        }
    }
}

// ---------------------------------------------------------------------------
// Flash attention on mma.sync, fp16 1-term: S = qh*kh, O += f16(P)*vh.
// 128-thread CTAs (4 warps, 64 q-rows), 3 CTAs/SM, 2-stage cp.async K/V ring.
// ---------------------------------------------------------------------------
#define FSTR     144             // 72 f16 row stride (odd 16B multiple)
#define FS_KV    9216            // Q: 64*144 @ 0; stages follow
#define FS_V_O   9216            // V offset within a stage
#define FS_STAGE 18432           // K (9216) + V (9216)
#define FS_TOTAL (FS_KV + 2 * FS_STAGE)   // 46080

__global__ __launch_bounds__(128, 3)
void flash_mma_kernel()
{
    extern __shared__ char smem[];
    const uint32_t sb = smem_u32(smem);
    const int tid  = threadIdx.x;
    const int lane = tid & 31;
    const int w    = tid >> 5;                               // 0..3
    const int qt   = (int)gridDim.x - 1 - (int)blockIdx.x;   // big tiles first
    const int bh   = blockIdx.y;
    const int q0   = qt * 64;
    const int nch  = qt + 1;                                 // 64-key chunks

    const size_t headoff = (size_t)bh * T_ * D_;
    const __half* Kh = g_Kh + headoff;
    const __half* Vh = g_Vh + headoff;

    auto issue_kv = [&](int kt, uint32_t stg) {
        #pragma unroll
        for (int i = 0; i < 4; i++) {
            const int e = tid + i * 128;     // 0..511
            const int row = e >> 3, u = e & 7;
            const size_t g = (size_t)(kt + row) * D_ + u * 8;
            const uint32_t o = (uint32_t)(row * FSTR + u * 16);
            CP_ASYNC16(stg + o,          Kh + g);
            CP_ASYNC16(stg + FS_V_O + o, Vh + g);
        }
    };

    issue_kv(0, sb + FS_KV);
    CP_COMMIT();

    // ---- stage Q tile (64 x 64) ----
    {
        const __half* Qh = g_Qh + headoff + (size_t)q0 * D_;
        #pragma unroll
        for (int i = 0; i < 4; i++) {
            const int e = tid + i * 128;
            const int row = e >> 3, u = e & 7;
            *(uint4*)(smem + row * FSTR + u * 16) = *(const uint4*)(Qh + row * 64 + u * 8);
        }
    }
    __syncthreads();

    // ---- Q fragments (registers for the whole loop) ----
    uint32_t qh[4][4];
    {
        const uint32_t qa = sb + (uint32_t)((16 * w + (lane & 15)) * FSTR + (lane >> 4) * 16);
        #pragma unroll
        for (int s = 0; s < 4; s++) ldsm_x4(qh[s], qa + s * 32);
    }

    float O[8][4];
    #pragma unroll
    for (int j = 0; j < 8; j++)
        #pragma unroll
        for (int r = 0; r < 4; r++) O[j][r] = 0.f;
    float m0 = -1e30f, m1 = -1e30f, l0 = 0.f, l1 = 0.f;

    const int wrow = q0 + 16 * w;
    const int r0g  = wrow + (lane >> 2);
    const int r1g  = r0g + 8;

    for (int c = 0; c < nch; ++c) {
        if (c + 1 < nch) {
            issue_kv((c + 1) * 64, sb + FS_KV + ((c + 1) & 1) * FS_STAGE);
            CP_COMMIT();
            CP_WAIT(1);
        } else {
            CP_WAIT(0);
        }
        __syncthreads();

        const int kt = c * 64;
        if (kt <= wrow + 15) {
            const uint32_t kbase = sb + FS_KV + (c & 1) * FS_STAGE;
            const int kmax = wrow + 15 - kt;

            // ---- S = qh * kh, s-outer ----
            float S[8][4];
            #pragma unroll
            for (int j = 0; j < 8; j++)
                #pragma unroll
                for (int r = 0; r < 4; r++) S[j][r] = 0.f;

            #pragma unroll
            for (int s = 0; s < 4; s++) {
                uint32_t kh[4][4];
                #pragma unroll
                for (int kp = 0; kp < 4; kp++) {
                    if (kp * 16 > kmax) continue;
                    const uint32_t ka = kbase
                        + (uint32_t)((kp * 16 + (lane & 15)) * FSTR + (lane >> 4) * 16)
                        + s * 32;
                    ldsm_x4(kh[kp], ka);
                }
                #pragma unroll
                for (int kp = 0; kp < 4; kp++) {
                    if (kp * 16 > kmax) continue;
                    uint32_t be[2] = {kh[kp][0], kh[kp][2]}, bo[2] = {kh[kp][1], kh[kp][3]};
                    mma_f16(S[2 * kp],     qh[s], be);
                    mma_f16(S[2 * kp + 1], qh[s], bo);
                }
            }

            // ---- causal mask ----
            if (kt + 63 > wrow) {
                #pragma unroll
                for (int j = 0; j < 8; j++) {
                    const int c0 = kt + j * 8 + (lane & 3) * 2;
                    if (c0 > r0g)     S[j][0] = -1e30f;
                    if (c0 + 1 > r0g) S[j][1] = -1e30f;
                    if (c0 > r1g)     S[j][2] = -1e30f;
                    if (c0 + 1 > r1g) S[j][3] = -1e30f;
                }
            }

            // ---- online softmax (base-2; scale folded into Q; raw EX2) ----
            float vmax0 = -1e30f, vmax1 = -1e30f;
            #pragma unroll
            for (int j = 0; j < 8; j++) {
                vmax0 = fmaxf(vmax0, fmaxf(S[j][0], S[j][1]));
                vmax1 = fmaxf(vmax1, fmaxf(S[j][2], S[j][3]));
            }
            vmax0 = fmaxf(vmax0, __shfl_xor_sync(0xffffffffu, vmax0, 1));
            vmax0 = fmaxf(vmax0, __shfl_xor_sync(0xffffffffu, vmax0, 2));
            vmax1 = fmaxf(vmax1, __shfl_xor_sync(0xffffffffu, vmax1, 1));
            vmax1 = fmaxf(vmax1, __shfl_xor_sync(0xffffffffu, vmax1, 2));

            const float mn0 = fmaxf(m0, vmax0);
            const float mn1 = fmaxf(m1, vmax1);
            const float c0f = ex2(m0 - mn0);
            const float c1f = ex2(m1 - mn1);
            m0 = mn0; m1 = mn1;

            float sum0 = 0.f, sum1 = 0.f;
            float P[8][4];
            #pragma unroll
            for (int j = 0; j < 8; j++) {
                P[j][0] = ex2(S[j][0] - mn0);
                P[j][1] = ex2(S[j][1] - mn0);
                P[j][2] = ex2(S[j][2] - mn1);
                P[j][3] = ex2(S[j][3] - mn1);
                sum0 += P[j][0] + P[j][1];
                sum1 += P[j][2] + P[j][3];
            }
            sum0 += __shfl_xor_sync(0xffffffffu, sum0, 1);
            sum0 += __shfl_xor_sync(0xffffffffu, sum0, 2);
            sum1 += __shfl_xor_sync(0xffffffffu, sum1, 1);
            sum1 += __shfl_xor_sync(0xffffffffu, sum1, 2);
            l0 = l0 * c0f + sum0;
            l1 = l1 * c1f + sum1;

            #pragma unroll
            for (int j = 0; j < 8; j++) {
                O[j][0] *= c0f; O[j][1] *= c0f;
                O[j][2] *= c1f; O[j][3] *= c1f;
            }

            // ---- P fragments ----
            uint32_t pa[4][4];
            #pragma unroll
            for (int kp = 0; kp < 4; kp++) {
                if (kp * 16 > kmax) continue;
                pa[kp][0] = pack_f16x2(P[2 * kp][0],     P[2 * kp][1]);
                pa[kp][1] = pack_f16x2(P[2 * kp][2],     P[2 * kp][3]);
                pa[kp][2] = pack_f16x2(P[2 * kp + 1][0], P[2 * kp + 1][1]);
                pa[kp][3] = pack_f16x2(P[2 * kp + 1][2], P[2 * kp + 1][3]);
            }

            // ---- O += P * vh ----
            #pragma unroll
            for (int kp = 0; kp < 4; kp++) {
                if (kp * 16 > kmax) continue;
                const uint32_t va0 = kbase + FS_V_O
                    + (uint32_t)((kp * 16 + (lane & 7) + ((lane >> 3) & 1) * 8) * FSTR
                                 + (lane >> 4) * 16);
                #pragma unroll
                for (int db = 0; db < 4; db++) {
                    uint32_t vh[4];
                    ldsm_x4_trans(vh, va0 + db * 32);
                    uint32_t bh0[2] = {vh[0], vh[1]}, bh1[2] = {vh[2], vh[3]};
                    mma_f16(O[2 * db],     pa[kp], bh0);
                    mma_f16(O[2 * db + 1], pa[kp], bh1);
                }
            }
        }
        __syncthreads();
    }

    // ---- epilogue: normalize, f16, write [B,T,C] ----
    const float inv0 = 1.f / l0;
    const float inv1 = 1.f / l1;
    const int bi = bh / H_;
    const int h  = bh % H_;
    #pragma unroll
    for (int jd = 0; jd < 8; jd++) {
        const int d0 = jd * 8 + (lane & 3) * 2;
        {
            const size_t idx = ((size_t)bi * T_ + r0g) * C_ + h * 64 + d0;
            *(uint32_t*)(g_Oh + idx) = pack_f16x2(O[jd][0] * inv0, O[jd][1] * inv0);
        }
        {
            const size_t idx = ((size_t)bi * T_ + r1g) * C_ + h * 64 + d0;
            *(uint32_t*)(g_Oh + idx) = pack_f16x2(O[jd][2] * inv1, O[jd][3] * inv1);
        }
    }
}

// ---------------------------------------------------------------------------
// Launch
// ---------------------------------------------------------------------------
extern "C" void kernel_launch(void* const* d_in, const int* in_sizes, int n_in,
                              void* d_out, int out_size)
{
    const float* x  = (const float*)d_in[0];
    const float* Wq = (const float*)d_in[1];
    const float* bq = (const float*)d_in[2];
    const float* Wk = (const float*)d_in[3];
    const float* bk = (const float*)d_in[4];
    const float* Wv = (const float*)d_in[5];
    const float* bv = (const float*)d_in[6];
    const float* Wo = (const float*)d_in[7];
    const float* bo = (const float*)d_in[8];

    static bool attr_set = false;
    if (!attr_set) {
        cudaFuncSetAttribute(tc_gemm_kernel<false>,
                             cudaFuncAttributeMaxDynamicSharedMemorySize, SM_TOTAL);
        cudaFuncSetAttribute(tc_gemm_kernel<true>,
                             cudaFuncAttributeMaxDynamicSharedMemorySize, SM_TOTAL);
        cudaFuncSetAttribute(flash_mma_kernel,
                             cudaFuncAttributeMaxDynamicSharedMemorySize, FS_TOTAL);
        attr_set = true;
    }

    cvt_x_kernel<<<(M_ * C_) / 1024, 1024>>>(x);
    cvt_w_kernel<<<dim3((C_ * C_) / 1024, 4), 1024>>>(Wq, Wk, Wv, Wo);

    tc_gemm_kernel<false><<<dim3(C_ / 128, M_ / 128, 3), 256, SM_TOTAL>>>(
        nullptr, bq, bk, bv);

    flash_mma_kernel<<<dim3(T_ / 64, B_ * H_), 128, FS_TOTAL>>>();

    tc_gemm_kernel<true><<<dim3(C_ / 128, M_ / 128, 1), 256, SM_TOTAL>>>(
        (float*)d_out, bo, nullptr, nullptr);
}